// round 1
// baseline (speedup 1.0000x reference)
#include <cuda_runtime.h>
#include <cstdint>

// Problem constants
#define BB 64
#define SS 1024
#define CC 512
#define SC (SS*CC)         // 524288 elements per batch
#define EPS 1e-5f

#define RED_CHUNKS 64

// Scratch (device globals: allocation-free per harness rules)
__device__ float2 g_partials[BB * RED_CHUNKS];
__device__ float2 g_stats[BB];
__device__ float  g_H[(size_t)BB * SC];   // normalized activations, tf32-rounded

// ---------------------------------------------------------------------------
// tf32 helpers
// ---------------------------------------------------------------------------
__device__ __forceinline__ uint32_t f32_to_tf32(float v) {
    uint32_t r;
    asm("cvt.rna.tf32.f32 %0, %1;" : "=r"(r) : "f"(v));
    return r;
}

__device__ __forceinline__ void mma_tf32(float* d, const uint32_t* a, const uint32_t* b) {
    asm volatile(
        "mma.sync.aligned.m16n8k8.row.col.f32.tf32.tf32.f32 "
        "{%0,%1,%2,%3}, {%4,%5,%6,%7}, {%8,%9}, {%0,%1,%2,%3};"
        : "+f"(d[0]), "+f"(d[1]), "+f"(d[2]), "+f"(d[3])
        : "r"(a[0]), "r"(a[1]), "r"(a[2]), "r"(a[3]),
          "r"(b[0]), "r"(b[1]));
}

// ---------------------------------------------------------------------------
// Kernel 1: per-batch partial sums (sum, sumsq). Deterministic fixed tree.
// grid = BB * RED_CHUNKS blocks, 256 threads.
// ---------------------------------------------------------------------------
__global__ void reduce_kernel(const float* __restrict__ x) {
    const int b     = blockIdx.x / RED_CHUNKS;
    const int chunk = blockIdx.x % RED_CHUNKS;
    const int n4    = SC / RED_CHUNKS / 4;   // 2048 float4 per block

    const float4* px = reinterpret_cast<const float4*>(x + (size_t)b * SC) + (size_t)chunk * n4;

    float s = 0.f, sq = 0.f;
    for (int i = threadIdx.x; i < n4; i += blockDim.x) {
        float4 v = px[i];
        s  += v.x + v.y + v.z + v.w;
        sq += v.x*v.x + v.y*v.y + v.z*v.z + v.w*v.w;
    }

    __shared__ float ss[8], ssq[8];
    #pragma unroll
    for (int o = 16; o > 0; o >>= 1) {
        s  += __shfl_down_sync(0xffffffff, s,  o);
        sq += __shfl_down_sync(0xffffffff, sq, o);
    }
    if ((threadIdx.x & 31) == 0) {
        ss [threadIdx.x >> 5] = s;
        ssq[threadIdx.x >> 5] = sq;
    }
    __syncthreads();
    if (threadIdx.x == 0) {
        float ts = 0.f, tsq = 0.f;
        #pragma unroll
        for (int w = 0; w < 8; w++) { ts += ss[w]; tsq += ssq[w]; }
        g_partials[blockIdx.x] = make_float2(ts, tsq);
    }
}

// ---------------------------------------------------------------------------
// Kernel 2: finalize stats (mu, rstd) per batch.
// ---------------------------------------------------------------------------
__global__ void stats_kernel() {
    int b = threadIdx.x;
    if (b < BB) {
        float s = 0.f, sq = 0.f;
        #pragma unroll 8
        for (int i = 0; i < RED_CHUNKS; i++) {
            float2 p = g_partials[b * RED_CHUNKS + i];
            s += p.x; sq += p.y;
        }
        float mu  = s / (float)SC;
        float var = fmaxf(sq / (float)SC - mu * mu, 0.f);
        g_stats[b] = make_float2(mu, rsqrtf(var + EPS));
    }
}

// ---------------------------------------------------------------------------
// Kernel 3: h = (x - mu)*rstd*ln_w + ln_b, rounded to tf32, stored to g_H.
// ---------------------------------------------------------------------------
__global__ void normalize_kernel(const float* __restrict__ x,
                                 const float* __restrict__ lnw,
                                 const float* __restrict__ lnb) {
    const int total4 = BB * SC / 4;          // 8,388,608 float4
    for (int i = blockIdx.x * blockDim.x + threadIdx.x; i < total4;
         i += gridDim.x * blockDim.x) {
        int b = i / (SC / 4);
        int r = i - b * (SC / 4);            // float4 index within [S,C]
        float2 st = g_stats[b];
        float4 xv = reinterpret_cast<const float4*>(x)[i];
        float4 wv = reinterpret_cast<const float4*>(lnw)[r];
        float4 bv = reinterpret_cast<const float4*>(lnb)[r];
        uint4 h;
        h.x = f32_to_tf32((xv.x - st.x) * st.y * wv.x + bv.x);
        h.y = f32_to_tf32((xv.y - st.x) * st.y * wv.y + bv.y);
        h.z = f32_to_tf32((xv.z - st.x) * st.y * wv.z + bv.z);
        h.w = f32_to_tf32((xv.w - st.x) * st.y * wv.w + bv.w);
        reinterpret_cast<uint4*>(g_H)[i] = h;
    }
}

// ---------------------------------------------------------------------------
// Kernel 4: per-batch GEMM  D[t,c] = sum_s W[t,s] * H[b,s,c]
// then out = x + relu(D + lin_b[t]).
// Block tile 128x128x16, 8 warps (2M x 4N), warp tile 64x32, m16n8k8 tf32.
// ---------------------------------------------------------------------------
#define BM 128
#define BN 128
#define BK 16
#define PAD_A 20     // As[m][k] stride -> conflict-free frag reads
#define PAD_B 136    // Bs[k][n] stride -> 8k+n spans all 32 banks

__global__ __launch_bounds__(256)
void gemm_kernel(const float* __restrict__ W,
                 const float* __restrict__ lin_b,
                 const float* __restrict__ x,
                 float* __restrict__ out) {
    __shared__ float As[BM][PAD_A];
    __shared__ float Bs[BK][PAD_B];

    const int b  = blockIdx.z;
    const int m0 = blockIdx.y * BM;
    const int n0 = blockIdx.x * BN;
    const float* __restrict__ Hb = g_H + (size_t)b * SC;

    const int tid  = threadIdx.x;
    const int lane = tid & 31;
    const int warp = tid >> 5;
    const int wm   = (warp >> 2) * 64;   // warp M offset (0/64)
    const int wn   = (warp & 3) * 32;    // warp N offset (0..96)

    float acc[4][4][4];
    #pragma unroll
    for (int i = 0; i < 4; i++)
        #pragma unroll
        for (int j = 0; j < 4; j++)
            #pragma unroll
            for (int k = 0; k < 4; k++) acc[i][j][k] = 0.f;

    // global->smem load mapping
    const int aRow = tid >> 2;          // 0..63 (+64 on 2nd iter)
    const int aCol = (tid & 3) * 4;     // float4 col within BK
    const int bRow = tid >> 5;          // 0..7  (+8 on 2nd iter)
    const int bCol = (tid & 31) * 4;    // float4 col within BN

    const int ar = lane >> 2;           // fragment row group
    const int ac = lane & 3;            // fragment col group

    for (int k0 = 0; k0 < SS; k0 += BK) {
        // A tile: W[m0+r][k0..k0+15], convert to tf32
        #pragma unroll
        for (int it = 0; it < 2; it++) {
            int r = aRow + it * 64;
            float4 v = *reinterpret_cast<const float4*>(W + (size_t)(m0 + r) * SS + k0 + aCol);
            As[r][aCol + 0] = __uint_as_float(f32_to_tf32(v.x));
            As[r][aCol + 1] = __uint_as_float(f32_to_tf32(v.y));
            As[r][aCol + 2] = __uint_as_float(f32_to_tf32(v.z));
            As[r][aCol + 3] = __uint_as_float(f32_to_tf32(v.w));
        }
        // B tile: H[b][k0+r][n0..n0+127] (already tf32-rounded)
        #pragma unroll
        for (int it = 0; it < 2; it++) {
            int r = bRow + it * 8;
            float4 v = *reinterpret_cast<const float4*>(Hb + (size_t)(k0 + r) * CC + n0 + bCol);
            Bs[r][bCol + 0] = v.x;
            Bs[r][bCol + 1] = v.y;
            Bs[r][bCol + 2] = v.z;
            Bs[r][bCol + 3] = v.w;
        }
        __syncthreads();

        #pragma unroll
        for (int ks = 0; ks < BK; ks += 8) {
            uint32_t afr[4][4], bfr[4][2];
            #pragma unroll
            for (int i = 0; i < 4; i++) {
                afr[i][0] = __float_as_uint(As[wm + i*16 + ar    ][ks + ac    ]);
                afr[i][1] = __float_as_uint(As[wm + i*16 + ar + 8][ks + ac    ]);
                afr[i][2] = __float_as_uint(As[wm + i*16 + ar    ][ks + ac + 4]);
                afr[i][3] = __float_as_uint(As[wm + i*16 + ar + 8][ks + ac + 4]);
            }
            #pragma unroll
            for (int j = 0; j < 4; j++) {
                bfr[j][0] = __float_as_uint(Bs[ks + ac    ][wn + j*8 + ar]);
                bfr[j][1] = __float_as_uint(Bs[ks + ac + 4][wn + j*8 + ar]);
            }
            #pragma unroll
            for (int i = 0; i < 4; i++)
                #pragma unroll
                for (int j = 0; j < 4; j++)
                    mma_tf32(acc[i][j], afr[i], bfr[j]);
        }
        __syncthreads();
    }

    // Epilogue: out[b,t,c] = x[b,t,c] + relu(acc + lin_b[t])
    const float* __restrict__ xb = x   + (size_t)b * SC;
    float* __restrict__       ob = out + (size_t)b * SC;
    const int ac2 = (lane & 3) * 2;

    #pragma unroll
    for (int i = 0; i < 4; i++) {
        int t0 = m0 + wm + i * 16 + ar;
        float bias0 = __ldg(lin_b + t0);
        float bias1 = __ldg(lin_b + t0 + 8);
        #pragma unroll
        for (int j = 0; j < 4; j++) {
            int c = n0 + wn + j * 8 + ac2;
            float2 xv0 = *reinterpret_cast<const float2*>(xb + (size_t)t0 * CC + c);
            float2 o0;
            o0.x = xv0.x + fmaxf(acc[i][j][0] + bias0, 0.f);
            o0.y = xv0.y + fmaxf(acc[i][j][1] + bias0, 0.f);
            *reinterpret_cast<float2*>(ob + (size_t)t0 * CC + c) = o0;

            float2 xv1 = *reinterpret_cast<const float2*>(xb + (size_t)(t0 + 8) * CC + c);
            float2 o1;
            o1.x = xv1.x + fmaxf(acc[i][j][2] + bias1, 0.f);
            o1.y = xv1.y + fmaxf(acc[i][j][3] + bias1, 0.f);
            *reinterpret_cast<float2*>(ob + (size_t)(t0 + 8) * CC + c) = o1;
        }
    }
}

// ---------------------------------------------------------------------------
// Launch
// ---------------------------------------------------------------------------
extern "C" void kernel_launch(void* const* d_in, const int* in_sizes, int n_in,
                              void* d_out, int out_size) {
    const float* x     = (const float*)d_in[0];
    const float* ln_w  = (const float*)d_in[1];
    const float* ln_b  = (const float*)d_in[2];
    const float* lin_w = (const float*)d_in[3];
    const float* lin_b = (const float*)d_in[4];
    float* out = (float*)d_out;

    reduce_kernel<<<BB * RED_CHUNKS, 256>>>(x);
    stats_kernel<<<1, 64>>>();
    normalize_kernel<<<8192, 256>>>(x, ln_w, ln_b);

    dim3 grid(CC / BN, SS / BM, BB);   // (4, 8, 64)
    gemm_kernel<<<grid, 256>>>(lin_w, lin_b, x, out);
}

// round 2
// speedup vs baseline: 1.1585x; 1.1585x over previous
#include <cuda_runtime.h>
#include <cstdint>

// Problem constants
#define BB 64
#define SS 1024
#define CC 512
#define SC (SS*CC)
#define EPS 1e-5f

#define RED_CHUNKS 64

// Scratch (device globals: allocation-free per harness rules)
__device__ float2 g_partials[BB * RED_CHUNKS];
__device__ float2 g_stats[BB];
__device__ float  g_H[(size_t)BB * SC];   // normalized activations, tf32-rounded

// ---------------------------------------------------------------------------
// tf32 helpers
// ---------------------------------------------------------------------------
__device__ __forceinline__ uint32_t f32_to_tf32(float v) {
    uint32_t r;
    asm("cvt.rna.tf32.f32 %0, %1;" : "=r"(r) : "f"(v));
    return r;
}

__device__ __forceinline__ void mma_tf32(float* d, const uint32_t* a, const uint32_t* b) {
    asm volatile(
        "mma.sync.aligned.m16n8k8.row.col.f32.tf32.tf32.f32 "
        "{%0,%1,%2,%3}, {%4,%5,%6,%7}, {%8,%9}, {%0,%1,%2,%3};"
        : "+f"(d[0]), "+f"(d[1]), "+f"(d[2]), "+f"(d[3])
        : "r"(a[0]), "r"(a[1]), "r"(a[2]), "r"(a[3]),
          "r"(b[0]), "r"(b[1]));
}

// ---------------------------------------------------------------------------
// Kernel 1: per-batch partial sums (sum, sumsq). Deterministic fixed tree.
// ---------------------------------------------------------------------------
__global__ void reduce_kernel(const float* __restrict__ x) {
    const int b     = blockIdx.x / RED_CHUNKS;
    const int chunk = blockIdx.x % RED_CHUNKS;
    const int n4    = SC / RED_CHUNKS / 4;   // 2048 float4 per block

    const float4* px = reinterpret_cast<const float4*>(x + (size_t)b * SC) + (size_t)chunk * n4;

    float s = 0.f, sq = 0.f;
    for (int i = threadIdx.x; i < n4; i += blockDim.x) {
        float4 v = px[i];
        s  += v.x + v.y + v.z + v.w;
        sq += v.x*v.x + v.y*v.y + v.z*v.z + v.w*v.w;
    }

    __shared__ float ss[8], ssq[8];
    #pragma unroll
    for (int o = 16; o > 0; o >>= 1) {
        s  += __shfl_down_sync(0xffffffff, s,  o);
        sq += __shfl_down_sync(0xffffffff, sq, o);
    }
    if ((threadIdx.x & 31) == 0) {
        ss [threadIdx.x >> 5] = s;
        ssq[threadIdx.x >> 5] = sq;
    }
    __syncthreads();
    if (threadIdx.x == 0) {
        float ts = 0.f, tsq = 0.f;
        #pragma unroll
        for (int w = 0; w < 8; w++) { ts += ss[w]; tsq += ssq[w]; }
        g_partials[blockIdx.x] = make_float2(ts, tsq);
    }
}

// ---------------------------------------------------------------------------
// Kernel 2: finalize stats (mu, rstd) per batch.
// ---------------------------------------------------------------------------
__global__ void stats_kernel() {
    int b = threadIdx.x;
    if (b < BB) {
        float s = 0.f, sq = 0.f;
        #pragma unroll 8
        for (int i = 0; i < RED_CHUNKS; i++) {
            float2 p = g_partials[b * RED_CHUNKS + i];
            s += p.x; sq += p.y;
        }
        float mu  = s / (float)SC;
        float var = fmaxf(sq / (float)SC - mu * mu, 0.f);
        g_stats[b] = make_float2(mu, rsqrtf(var + EPS));
    }
}

// ---------------------------------------------------------------------------
// Kernel 3: h = (x - mu)*rstd*ln_w + ln_b, tf32-rounded. 2D grid (no divides).
// ---------------------------------------------------------------------------
__global__ void normalize_kernel(const float* __restrict__ x,
                                 const float* __restrict__ lnw,
                                 const float* __restrict__ lnb) {
    const int b = blockIdx.y;
    const int r = blockIdx.x * blockDim.x + threadIdx.x;   // float4 idx in [S,C]
    const size_t i = (size_t)b * (SC / 4) + r;
    float2 st = g_stats[b];
    float4 xv = reinterpret_cast<const float4*>(x)[i];
    float4 wv = reinterpret_cast<const float4*>(lnw)[r];
    float4 bv = reinterpret_cast<const float4*>(lnb)[r];
    uint4 h;
    h.x = f32_to_tf32((xv.x - st.x) * st.y * wv.x + bv.x);
    h.y = f32_to_tf32((xv.y - st.x) * st.y * wv.y + bv.y);
    h.z = f32_to_tf32((xv.z - st.x) * st.y * wv.z + bv.z);
    h.w = f32_to_tf32((xv.w - st.x) * st.y * wv.w + bv.w);
    reinterpret_cast<uint4*>(g_H)[i] = h;
}

// ---------------------------------------------------------------------------
// Kernel 4: per-batch GEMM  D[t,c] = sum_s W[t,s] * H[b,s,c]
// out = x + relu(D + lin_b[t]).
// 128x128x16 tile, 8 warps (2Mx4N), warp 64x32, m16n8k8 tf32.
// Double-buffered smem + register-staged prefetch.
// A stored fragment-major + XOR swizzle -> one LDS.128 per A frag.
// B kept [k][n] with pad 136 (conflict-free LDS.32).
// ---------------------------------------------------------------------------
#define BM 128
#define BN 128
#define BK 16
#define PAD_B 136
#define NTILES (SS / BK)   // 64

__global__ __launch_bounds__(256, 2)
void gemm_kernel(const float* __restrict__ W,
                 const float* __restrict__ lin_b,
                 const float* __restrict__ x,
                 float* __restrict__ out) {
    // A: 16 segments (g=0..7 x ks=0..1), each 32 chunks x 4 floats (frag-major)
    __shared__ float As[2][2048];
    __shared__ float Bs[2][BK][PAD_B];

    const int b  = blockIdx.z;
    const int m0 = blockIdx.y * BM;
    const int n0 = blockIdx.x * BN;
    const float* __restrict__ Hb = g_H + (size_t)b * SC;

    const int tid  = threadIdx.x;
    const int lane = tid & 31;
    const int warp = tid >> 5;
    const int wm   = (warp >> 2) * 64;
    const int wn   = (warp & 3) * 32;

    float acc[4][4][4];
    #pragma unroll
    for (int i = 0; i < 4; i++)
        #pragma unroll
        for (int j = 0; j < 4; j++)
            #pragma unroll
            for (int k = 0; k < 4; k++) acc[i][j][k] = 0.f;

    // --- loader indices ---
    // A: thread loads W[m0 + aRow + it*64][k0 + q*4 .. +3], q = tid&3
    const int aRow  = tid >> 2;
    const int q     = tid & 3;
    const int aks   = q >> 1;       // which 8-k half
    const int ahalf = q & 1;        // c8/4
    // B: thread loads H[k0 + bRow + it*8][n0 + bCol .. +3]
    const int bRow = tid >> 5;
    const int bCol = (tid & 31) * 4;

    // --- fragment indices ---
    const int ar = lane >> 2;
    const int ac = lane & 3;
    const int ldChunk = lane ^ (lane >> 3);   // swizzled chunk for LDS.128

    const float* Wbase = W + (size_t)m0 * SS;

    // helpers (macros to keep everything in registers)
    float4 av[2], bv[2];

    #define LDG_TILE(k0)                                                          \
        do {                                                                      \
            av[0] = *reinterpret_cast<const float4*>(Wbase + (size_t)(aRow)      * SS + (k0) + q * 4); \
            av[1] = *reinterpret_cast<const float4*>(Wbase + (size_t)(aRow + 64) * SS + (k0) + q * 4); \
            bv[0] = *reinterpret_cast<const float4*>(Hb + (size_t)((k0) + bRow)     * CC + n0 + bCol); \
            bv[1] = *reinterpret_cast<const float4*>(Hb + (size_t)((k0) + bRow + 8) * CC + n0 + bCol); \
        } while (0)

    #define STS_TILE(buf)                                                         \
        do {                                                                      \
            _Pragma("unroll")                                                     \
            for (int it = 0; it < 2; it++) {                                      \
                int r  = (aRow + it * 64) & 15;                                   \
                int g  = (aRow + it * 64) >> 4;                                   \
                int slot = (r >> 3) + 2 * ahalf;                                  \
                int base = (g * 2 + aks) * 128;                                   \
                const float* vv = reinterpret_cast<const float*>(&av[it]);        \
                _Pragma("unroll")                                                 \
                for (int e = 0; e < 4; e++) {                                     \
                    int le = (r & 7) * 4 + e;                                     \
                    int ch = le ^ (le >> 3);                                      \
                    As[buf][base + ch * 4 + slot] = __uint_as_float(f32_to_tf32(vv[e])); \
                }                                                                 \
            }                                                                     \
            _Pragma("unroll")                                                     \
            for (int it = 0; it < 2; it++) {                                      \
                float* dst = &Bs[buf][bRow + it * 8][bCol];                       \
                const float* vv = reinterpret_cast<const float*>(&bv[it]);        \
                dst[0] = vv[0]; dst[1] = vv[1]; dst[2] = vv[2]; dst[3] = vv[3];   \
            }                                                                     \
        } while (0)

    // prologue: tile 0 -> buf 0
    LDG_TILE(0);
    STS_TILE(0);
    __syncthreads();

    for (int t = 0; t < NTILES; t++) {
        const int buf = t & 1;
        if (t + 1 < NTILES) LDG_TILE((t + 1) * BK);

        // compute tile t
        #pragma unroll
        for (int kk = 0; kk < 2; kk++) {
            uint4 afr[4];
            #pragma unroll
            for (int i = 0; i < 4; i++) {
                int seg = ((wm >> 4) + i) * 256 + kk * 128;
                afr[i] = *reinterpret_cast<const uint4*>(&As[buf][seg + ldChunk * 4]);
            }
            uint32_t bfr[4][2];
            #pragma unroll
            for (int j = 0; j < 4; j++) {
                bfr[j][0] = __float_as_uint(Bs[buf][kk * 8 + ac    ][wn + j * 8 + ar]);
                bfr[j][1] = __float_as_uint(Bs[buf][kk * 8 + ac + 4][wn + j * 8 + ar]);
            }
            #pragma unroll
            for (int i = 0; i < 4; i++)
                #pragma unroll
                for (int j = 0; j < 4; j++)
                    mma_tf32(acc[i][j], reinterpret_cast<const uint32_t*>(&afr[i]), bfr[j]);
        }

        if (t + 1 < NTILES) STS_TILE(buf ^ 1);
        __syncthreads();
    }

    // Epilogue: out[b,t,c] = x[b,t,c] + relu(acc + lin_b[t])
    const float* __restrict__ xb = x   + (size_t)b * SC;
    float* __restrict__       ob = out + (size_t)b * SC;
    const int ac2 = (lane & 3) * 2;

    #pragma unroll
    for (int i = 0; i < 4; i++) {
        int t0 = m0 + wm + i * 16 + ar;
        float bias0 = __ldg(lin_b + t0);
        float bias1 = __ldg(lin_b + t0 + 8);
        #pragma unroll
        for (int j = 0; j < 4; j++) {
            int c = n0 + wn + j * 8 + ac2;
            float2 xv0 = *reinterpret_cast<const float2*>(xb + (size_t)t0 * CC + c);
            float2 o0;
            o0.x = xv0.x + fmaxf(acc[i][j][0] + bias0, 0.f);
            o0.y = xv0.y + fmaxf(acc[i][j][1] + bias0, 0.f);
            *reinterpret_cast<float2*>(ob + (size_t)t0 * CC + c) = o0;

            float2 xv1 = *reinterpret_cast<const float2*>(xb + (size_t)(t0 + 8) * CC + c);
            float2 o1;
            o1.x = xv1.x + fmaxf(acc[i][j][2] + bias1, 0.f);
            o1.y = xv1.y + fmaxf(acc[i][j][3] + bias1, 0.f);
            *reinterpret_cast<float2*>(ob + (size_t)(t0 + 8) * CC + c) = o1;
        }
    }
}

// ---------------------------------------------------------------------------
// Launch
// ---------------------------------------------------------------------------
extern "C" void kernel_launch(void* const* d_in, const int* in_sizes, int n_in,
                              void* d_out, int out_size) {
    const float* x     = (const float*)d_in[0];
    const float* ln_w  = (const float*)d_in[1];
    const float* ln_b  = (const float*)d_in[2];
    const float* lin_w = (const float*)d_in[3];
    const float* lin_b = (const float*)d_in[4];
    float* out = (float*)d_out;

    reduce_kernel<<<BB * RED_CHUNKS, 256>>>(x);
    stats_kernel<<<1, 64>>>();
    normalize_kernel<<<dim3(SC / 4 / 256, BB), 256>>>(x, ln_w, ln_b);

    dim3 grid(CC / BN, SS / BM, BB);   // (4, 8, 64)
    gemm_kernel<<<grid, 256>>>(lin_w, lin_b, x, out);
}

// round 4
// speedup vs baseline: 1.4325x; 1.2365x over previous
#include <cuda_runtime.h>
#include <cuda_fp16.h>
#include <cstdint>

// Problem constants
#define BB 64
#define SS 1024
#define CC 512
#define SC (SS*CC)
#define NN (BB*CC)          // 32768 = total N of the big GEMM
#define EPS 1e-5f
#define RED_CHUNKS 64

// Scratch (device globals: allocation-free per harness rules)
__device__ float2 g_partials[BB * RED_CHUNKS];
__device__ float2 g_stats[BB];
__device__ __half g_Ht[(size_t)NN * SS];   // H^T: [n = b*512+c][s], fp16

// ---------------------------------------------------------------------------
// helpers
// ---------------------------------------------------------------------------
__device__ __forceinline__ uint32_t smem_to_u32(const void* p) {
    uint32_t a;
    asm("{ .reg .u64 t; cvta.to.shared.u64 t, %1; cvt.u32.u64 %0, t; }" : "=r"(a) : "l"(p));
    return a;
}

__device__ __forceinline__ void ldmatrix_x4(uint32_t& r0, uint32_t& r1,
                                            uint32_t& r2, uint32_t& r3, uint32_t addr) {
    asm volatile("ldmatrix.sync.aligned.m8n8.x4.shared.b16 {%0,%1,%2,%3}, [%4];"
                 : "=r"(r0), "=r"(r1), "=r"(r2), "=r"(r3) : "r"(addr));
}

__device__ __forceinline__ void mma_f16(float* d, const uint32_t* a,
                                        uint32_t b0, uint32_t b1) {
    asm volatile(
        "mma.sync.aligned.m16n8k16.row.col.f32.f16.f16.f32 "
        "{%0,%1,%2,%3}, {%4,%5,%6,%7}, {%8,%9}, {%0,%1,%2,%3};"
        : "+f"(d[0]), "+f"(d[1]), "+f"(d[2]), "+f"(d[3])
        : "r"(a[0]), "r"(a[1]), "r"(a[2]), "r"(a[3]), "r"(b0), "r"(b1));
}

// ---------------------------------------------------------------------------
// Kernel 1: per-batch partial sums (sum, sumsq). Deterministic fixed tree.
// ---------------------------------------------------------------------------
__global__ void reduce_kernel(const float* __restrict__ x) {
    const int b     = blockIdx.x / RED_CHUNKS;
    const int chunk = blockIdx.x % RED_CHUNKS;
    const int n4    = SC / RED_CHUNKS / 4;

    const float4* px = reinterpret_cast<const float4*>(x + (size_t)b * SC) + (size_t)chunk * n4;

    float s = 0.f, sq = 0.f;
    for (int i = threadIdx.x; i < n4; i += blockDim.x) {
        float4 v = px[i];
        s  += v.x + v.y + v.z + v.w;
        sq += v.x*v.x + v.y*v.y + v.z*v.z + v.w*v.w;
    }
    __shared__ float ss[8], ssq[8];
    #pragma unroll
    for (int o = 16; o > 0; o >>= 1) {
        s  += __shfl_down_sync(0xffffffff, s,  o);
        sq += __shfl_down_sync(0xffffffff, sq, o);
    }
    if ((threadIdx.x & 31) == 0) { ss[threadIdx.x >> 5] = s; ssq[threadIdx.x >> 5] = sq; }
    __syncthreads();
    if (threadIdx.x == 0) {
        float ts = 0.f, tsq = 0.f;
        #pragma unroll
        for (int w = 0; w < 8; w++) { ts += ss[w]; tsq += ssq[w]; }
        g_partials[blockIdx.x] = make_float2(ts, tsq);
    }
}

__global__ void stats_kernel() {
    int b = threadIdx.x;
    if (b < BB) {
        float s = 0.f, sq = 0.f;
        #pragma unroll 8
        for (int i = 0; i < RED_CHUNKS; i++) {
            float2 p = g_partials[b * RED_CHUNKS + i];
            s += p.x; sq += p.y;
        }
        float mu  = s / (float)SC;
        float var = fmaxf(sq / (float)SC - mu * mu, 0.f);
        g_stats[b] = make_float2(mu, rsqrtf(var + EPS));
    }
}

// ---------------------------------------------------------------------------
// Kernel 3: fused LayerNorm + transpose -> g_Ht[n = b*512+c][s], fp16.
// 32x32 tiles via smem. block (32,8), grid (S/32, C/32, B).
// ---------------------------------------------------------------------------
__global__ void normalize_t_kernel(const float* __restrict__ x,
                                   const float* __restrict__ lnw,
                                   const float* __restrict__ lnb) {
    __shared__ float tile[32][33];
    const int b  = blockIdx.z;
    const int s0 = blockIdx.x * 32;
    const int c0 = blockIdx.y * 32;
    const float2 st = g_stats[b];

    #pragma unroll
    for (int i = 0; i < 4; i++) {
        int s = s0 + threadIdx.y + i * 8;
        int c = c0 + threadIdx.x;
        float v  = x  [(size_t)b * SC + (size_t)s * CC + c];
        float w  = lnw[(size_t)s * CC + c];
        float bb = lnb[(size_t)s * CC + c];
        tile[threadIdx.y + i * 8][threadIdx.x] = (v - st.x) * st.y * w + bb;
    }
    __syncthreads();
    #pragma unroll
    for (int i = 0; i < 4; i++) {
        int c = c0 + threadIdx.y + i * 8;
        int s = s0 + threadIdx.x;
        g_Ht[(size_t)(b * CC + c) * SS + s] = __float2half_rn(tile[threadIdx.x][threadIdx.y + i * 8]);
    }
}

// ---------------------------------------------------------------------------
// Kernel 4: fp16 GEMM  D[M=1024, N=32768] = W(fp16-cvt) x Ht^T, K=1024, fp32 acc.
// CTA tile 128(M) x 256(N) x 32(K). 8 warps (2M x 4N), warp tile 64x64.
// A, B in smem with 80B row stride (conflict-free ldmatrix, (5r+c) mod 8 perm).
// Double-buffered, register-staged LDG prefetch. Epilogue fuses bias+relu+residual.
// ---------------------------------------------------------------------------
#define BM 128
#define BN 256
#define BK 32
#define NT (SS / BK)           // 32 k-tiles
#define ROWB 80                // bytes per smem row (32 halves + 16B pad)
#define A_BYTES (BM * ROWB)    // 10240
#define B_BYTES (BN * ROWB)    // 20480
#define OFF_B (2 * A_BYTES)    // 20480
#define GSMEM (2 * A_BYTES + 2 * B_BYTES)  // 61440

__global__ __launch_bounds__(256, 1)
void gemm_f16(const float* __restrict__ W, const float* __restrict__ linb,
              const float* __restrict__ x, float* __restrict__ out)
{
    extern __shared__ char smem[];
    const uint32_t sb = smem_to_u32(smem);

    const int tid  = threadIdx.x;
    const int lane = tid & 31;
    const int wid  = tid >> 5;
    const int wm   = (wid >> 2) * 64;       // 0 / 64
    const int wn   = (wid & 3) * 64;        // 0..192
    const int m0   = blockIdx.x * BM;
    const int n0   = blockIdx.y * BN;

    float acc[4][8][4];
    #pragma unroll
    for (int i = 0; i < 4; i++)
        #pragma unroll
        for (int j = 0; j < 8; j++)
            #pragma unroll
            for (int k = 0; k < 4; k++) acc[i][j][k] = 0.f;

    // ---- loader indices ----
    // A: thread -> row tid>>1 (0..127), half-row (tid&1): 16 floats = 4 float4
    const int aRow = tid >> 1;
    const int aOff = (tid & 1) * 16;        // float offset within 32
    const float* Wrow = W + (size_t)(m0 + aRow) * SS + aOff;
    uint32_t aSts = sb + aRow * ROWB + aOff * 2;       // halves -> x2 bytes
    // B: thread -> row tid (0..255), 4 x 16B chunks
    const __half* Hrow = g_Ht + (size_t)(n0 + tid) * SS;
    uint32_t bSts = sb + OFF_B + tid * ROWB;

    // ---- ldmatrix base addresses ----
    const int l15 = lane & 15;
    const int lhi = lane >> 4;
    uint32_t aLd = sb + (wm + l15) * ROWB + lhi * 16;
    uint32_t bLd = sb + OFF_B + (wn + l15) * ROWB + lhi * 16;

    float4 av[4];
    uint4  bv[4];

    #define LDG_T(k0)                                                           \
        do {                                                                    \
            _Pragma("unroll")                                                   \
            for (int i = 0; i < 4; i++)                                         \
                av[i] = *reinterpret_cast<const float4*>(Wrow + (k0) + i * 4);  \
            _Pragma("unroll")                                                   \
            for (int i = 0; i < 4; i++)                                         \
                bv[i] = *reinterpret_cast<const uint4*>(Hrow + (k0) + i * 8);   \
        } while (0)

    #define STS_T(buf)                                                          \
        do {                                                                    \
            _Pragma("unroll")                                                   \
            for (int i = 0; i < 4; i++) {                                       \
                __half2 h0 = __floats2half2_rn(av[i].x, av[i].y);               \
                __half2 h1 = __floats2half2_rn(av[i].z, av[i].w);               \
                uint2 pk;                                                       \
                pk.x = *reinterpret_cast<uint32_t*>(&h0);                       \
                pk.y = *reinterpret_cast<uint32_t*>(&h1);                       \
                asm volatile("st.shared.v2.b32 [%0], {%1,%2};"                  \
                    :: "r"(aSts + (buf) * A_BYTES + i * 8), "r"(pk.x), "r"(pk.y) : "memory"); \
            }                                                                   \
            _Pragma("unroll")                                                   \
            for (int i = 0; i < 4; i++)                                         \
                asm volatile("st.shared.v4.b32 [%0], {%1,%2,%3,%4};"            \
                    :: "r"(bSts + (buf) * B_BYTES + i * 16),                    \
                       "r"(bv[i].x), "r"(bv[i].y), "r"(bv[i].z), "r"(bv[i].w) : "memory"); \
        } while (0)

    LDG_T(0);
    STS_T(0);
    __syncthreads();

    for (int t = 0; t < NT; t++) {
        const int buf = t & 1;
        if (t + 1 < NT) LDG_T((t + 1) * BK);

        #pragma unroll
        for (int ks = 0; ks < 2; ks++) {
            uint32_t a[4][4], bm_[4][4];
            #pragma unroll
            for (int i = 0; i < 4; i++)
                ldmatrix_x4(a[i][0], a[i][1], a[i][2], a[i][3],
                            aLd + buf * A_BYTES + i * 16 * ROWB + ks * 32);
            #pragma unroll
            for (int j = 0; j < 4; j++)
                ldmatrix_x4(bm_[j][0], bm_[j][1], bm_[j][2], bm_[j][3],
                            bLd + buf * B_BYTES + j * 16 * ROWB + ks * 32);
            #pragma unroll
            for (int i = 0; i < 4; i++)
                #pragma unroll
                for (int j = 0; j < 4; j++) {
                    mma_f16(acc[i][2*j    ], a[i], bm_[j][0], bm_[j][2]);
                    mma_f16(acc[i][2*j + 1], a[i], bm_[j][1], bm_[j][3]);
                }
        }

        if (t + 1 < NT) STS_T(buf ^ 1);
        __syncthreads();
    }

    // Epilogue: n -> (batch b, channel c); whole CTA sits in one batch.
    const int bidx = n0 >> 9;
    const int c0   = n0 & 511;
    const float* xb = x   + (size_t)bidx * SC;
    float*       ob = out + (size_t)bidx * SC;

    #pragma unroll
    for (int i = 0; i < 4; i++) {
        const int t0 = m0 + wm + i * 16 + (lane >> 2);
        const float bias0 = __ldg(linb + t0);
        const float bias1 = __ldg(linb + t0 + 8);
        #pragma unroll
        for (int j = 0; j < 8; j++) {
            const int c = c0 + wn + j * 8 + (lane & 3) * 2;
            float2 xv0 = *reinterpret_cast<const float2*>(xb + (size_t)t0 * CC + c);
            float2 o0;
            o0.x = xv0.x + fmaxf(acc[i][j][0] + bias0, 0.f);
            o0.y = xv0.y + fmaxf(acc[i][j][1] + bias0, 0.f);
            *reinterpret_cast<float2*>(ob + (size_t)t0 * CC + c) = o0;

            float2 xv1 = *reinterpret_cast<const float2*>(xb + (size_t)(t0 + 8) * CC + c);
            float2 o1;
            o1.x = xv1.x + fmaxf(acc[i][j][2] + bias1, 0.f);
            o1.y = xv1.y + fmaxf(acc[i][j][3] + bias1, 0.f);
            *reinterpret_cast<float2*>(ob + (size_t)(t0 + 8) * CC + c) = o1;
        }
    }
}

// ---------------------------------------------------------------------------
// Launch
// ---------------------------------------------------------------------------
extern "C" void kernel_launch(void* const* d_in, const int* in_sizes, int n_in,
                              void* d_out, int out_size) {
    const float* x     = (const float*)d_in[0];
    const float* ln_w  = (const float*)d_in[1];
    const float* ln_b  = (const float*)d_in[2];
    const float* lin_w = (const float*)d_in[3];
    const float* lin_b = (const float*)d_in[4];
    float* out = (float*)d_out;

    cudaFuncSetAttribute(gemm_f16, cudaFuncAttributeMaxDynamicSharedMemorySize, GSMEM);

    reduce_kernel<<<BB * RED_CHUNKS, 256>>>(x);
    stats_kernel<<<1, 64>>>();
    normalize_t_kernel<<<dim3(SS / 32, CC / 32, BB), dim3(32, 8)>>>(x, ln_w, ln_b);

    // M=1024 (8 x 128), N=32768 (128 x 256)
    gemm_f16<<<dim3(8, 128), 256, GSMEM>>>(lin_w, lin_b, x, out);
}

// round 6
// speedup vs baseline: 1.7164x; 1.1982x over previous
#include <cuda_runtime.h>
#include <cuda_fp16.h>
#include <cstdint>

// Problem constants
#define BB 64
#define SS 1024
#define CC 512
#define SC (SS*CC)
#define NN (BB*CC)          // 32768 = total N of the big GEMM
#define EPS 1e-5f
#define RED_CHUNKS 64
#define BK 32               // k-tile (halves)
#define NT (SS / BK)        // 32 k-tiles

// Scratch (device globals; 16B-aligned for cp.async / uint4)
__device__ float2 g_partials[BB * RED_CHUNKS];
__device__ float2 g_stats[BB];
// K-panel layouts: [(kt*ROWS + row)*32 + ks], fp16
__device__ __align__(16) __half g_Hp[(size_t)NN * SS];     // B panels (64MB)
__device__ __align__(16) __half g_Wh[(size_t)SS * SS];     // A panels (2MB)

// ---------------------------------------------------------------------------
// helpers
// ---------------------------------------------------------------------------
__device__ __forceinline__ uint32_t smem_to_u32(const void* p) {
    uint32_t a;
    asm("{ .reg .u64 t; cvta.to.shared.u64 t, %1; cvt.u32.u64 %0, t; }" : "=r"(a) : "l"(p));
    return a;
}
__device__ __forceinline__ void ldmatrix_x4(uint32_t& r0, uint32_t& r1,
                                            uint32_t& r2, uint32_t& r3, uint32_t addr) {
    asm volatile("ldmatrix.sync.aligned.m8n8.x4.shared.b16 {%0,%1,%2,%3}, [%4];"
                 : "=r"(r0), "=r"(r1), "=r"(r2), "=r"(r3) : "r"(addr));
}
__device__ __forceinline__ void mma_f16(float* d, const uint32_t* a,
                                        uint32_t b0, uint32_t b1) {
    asm volatile(
        "mma.sync.aligned.m16n8k16.row.col.f32.f16.f16.f32 "
        "{%0,%1,%2,%3}, {%4,%5,%6,%7}, {%8,%9}, {%0,%1,%2,%3};"
        : "+f"(d[0]), "+f"(d[1]), "+f"(d[2]), "+f"(d[3])
        : "r"(a[0]), "r"(a[1]), "r"(a[2]), "r"(a[3]), "r"(b0), "r"(b1));
}
__device__ __forceinline__ void cp16(uint32_t dst, const void* src) {
    asm volatile("cp.async.cg.shared.global [%0], [%1], 16;" :: "r"(dst), "l"(src));
}
#define CP_COMMIT() asm volatile("cp.async.commit_group;" ::: "memory")
#define CP_WAIT1()  asm volatile("cp.async.wait_group 1;" ::: "memory")

__device__ __forceinline__ uint32_t pack2(float a, float b) {
    __half2 h = __floats2half2_rn(a, b);
    return *reinterpret_cast<uint32_t*>(&h);
}

// ---------------------------------------------------------------------------
// Kernel 1: per-batch partial sums (sum, sumsq). Deterministic fixed tree.
// ---------------------------------------------------------------------------
__global__ void reduce_kernel(const float* __restrict__ x) {
    const int b     = blockIdx.x / RED_CHUNKS;
    const int chunk = blockIdx.x % RED_CHUNKS;
    const int n4    = SC / RED_CHUNKS / 4;
    const float4* px = reinterpret_cast<const float4*>(x + (size_t)b * SC) + (size_t)chunk * n4;

    float s = 0.f, sq = 0.f;
    for (int i = threadIdx.x; i < n4; i += blockDim.x) {
        float4 v = px[i];
        s  += v.x + v.y + v.z + v.w;
        sq += v.x*v.x + v.y*v.y + v.z*v.z + v.w*v.w;
    }
    __shared__ float ss[8], ssq[8];
    #pragma unroll
    for (int o = 16; o > 0; o >>= 1) {
        s  += __shfl_down_sync(0xffffffff, s,  o);
        sq += __shfl_down_sync(0xffffffff, sq, o);
    }
    if ((threadIdx.x & 31) == 0) { ss[threadIdx.x >> 5] = s; ssq[threadIdx.x >> 5] = sq; }
    __syncthreads();
    if (threadIdx.x == 0) {
        float ts = 0.f, tsq = 0.f;
        #pragma unroll
        for (int w = 0; w < 8; w++) { ts += ss[w]; tsq += ssq[w]; }
        g_partials[blockIdx.x] = make_float2(ts, tsq);
    }
}

__global__ void stats_kernel() {
    int b = threadIdx.x;
    if (b < BB) {
        float s = 0.f, sq = 0.f;
        #pragma unroll 8
        for (int i = 0; i < RED_CHUNKS; i++) {
            float2 p = g_partials[b * RED_CHUNKS + i];
            s += p.x; sq += p.y;
        }
        float mu  = s / (float)SC;
        float var = fmaxf(sq / (float)SC - mu * mu, 0.f);
        g_stats[b] = make_float2(mu, rsqrtf(var + EPS));
    }
}

// ---------------------------------------------------------------------------
// Kernel 2b: convert W (fp32 [m][s]) -> g_Wh fp16 K-panels [(kt*1024+m)*32+ks].
// 32x32 tiles. 128 uint4 write tasks (idx < 128 guard!). grid (32,32), block (32,8).
// ---------------------------------------------------------------------------
__global__ void convert_w_kernel(const float* __restrict__ W) {
    __shared__ float tile[32][33];
    const int m0 = blockIdx.x * 32;
    const int s0 = blockIdx.y * 32;
    #pragma unroll
    for (int i = 0; i < 4; i++)
        tile[threadIdx.y + i * 8][threadIdx.x] =
            W[(size_t)(m0 + threadIdx.y + i * 8) * SS + s0 + threadIdx.x];
    __syncthreads();
    const int idx = threadIdx.y * 32 + threadIdx.x;
    if (idx < 128) {
        const int m     = idx >> 2;      // 0..31
        const int chunk = idx & 3;       // 0..3
        const int kt    = s0 >> 5;
        uint4 pk;
        pk.x = pack2(tile[m][chunk*8+0], tile[m][chunk*8+1]);
        pk.y = pack2(tile[m][chunk*8+2], tile[m][chunk*8+3]);
        pk.z = pack2(tile[m][chunk*8+4], tile[m][chunk*8+5]);
        pk.w = pack2(tile[m][chunk*8+6], tile[m][chunk*8+7]);
        *reinterpret_cast<uint4*>(g_Wh + ((size_t)kt * SS + m0 + m) * 32 + chunk * 8) = pk;
    }
}

// ---------------------------------------------------------------------------
// Kernel 3: fused LayerNorm + transpose -> g_Hp K-panels [(kt*NN + n)*32 + ks].
// block (32,8), grid (S/32, C/32, B). 128 uint4 write tasks (idx < 128 guard!).
// ---------------------------------------------------------------------------
__global__ void normalize_t_kernel(const float* __restrict__ x,
                                   const float* __restrict__ lnw,
                                   const float* __restrict__ lnb) {
    __shared__ float tile[32][33];     // [s_local][c_local]
    const int b  = blockIdx.z;
    const int s0 = blockIdx.x * 32;
    const int c0 = blockIdx.y * 32;
    const float2 st = g_stats[b];

    #pragma unroll
    for (int i = 0; i < 4; i++) {
        int s = s0 + threadIdx.y + i * 8;
        int c = c0 + threadIdx.x;
        float v  = x  [(size_t)b * SC + (size_t)s * CC + c];
        float w  = lnw[(size_t)s * CC + c];
        float bb = lnb[(size_t)s * CC + c];
        tile[threadIdx.y + i * 8][threadIdx.x] = (v - st.x) * st.y * w + bb;
    }
    __syncthreads();
    const int idx = threadIdx.y * 32 + threadIdx.x;
    if (idx < 128) {
        const int c     = idx >> 2;      // 0..31
        const int chunk = idx & 3;       // 0..3
        const int kt    = s0 >> 5;
        const int n     = b * CC + c0 + c;
        uint4 pk;
        pk.x = pack2(tile[chunk*8+0][c], tile[chunk*8+1][c]);
        pk.y = pack2(tile[chunk*8+2][c], tile[chunk*8+3][c]);
        pk.z = pack2(tile[chunk*8+4][c], tile[chunk*8+5][c]);
        pk.w = pack2(tile[chunk*8+6][c], tile[chunk*8+7][c]);
        *reinterpret_cast<uint4*>(g_Hp + ((size_t)kt * NN + n) * 32 + chunk * 8) = pk;
    }
}

// ---------------------------------------------------------------------------
// Kernel 4: fp16 GEMM, fp32 acc. D[1024, 32768] = Wh x Hp^T, K=1024.
// CTA 128(M) x 256(N) x 32(K). 8 warps (2M x 4N), warp 64x64.
// 3-stage cp.async pipeline from contiguous K-panels.
// smem rows 80B (conflict-free ldmatrix). Epilogue: out = x + relu(D + bias).
// ---------------------------------------------------------------------------
#define BM 128
#define BN 256
#define AST (BM * 80)              // 10240 B per A stage
#define BST (BN * 80)              // 20480 B per B stage
#define OFF_BS (3 * AST)           // B stages base
#define GSMEM (3 * (AST + BST))    // 92160 B

__global__ __launch_bounds__(256, 1)
void gemm_f16(const float* __restrict__ linb,
              const float* __restrict__ x, float* __restrict__ out)
{
    extern __shared__ char smem[];
    const uint32_t sb = smem_to_u32(smem);

    const int tid  = threadIdx.x;
    const int lane = tid & 31;
    const int wid  = tid >> 5;
    const int wm   = (wid >> 2) * 64;
    const int wn   = (wid & 3) * 64;
    const int m0   = blockIdx.x * BM;
    const int n0   = blockIdx.y * BN;

    float acc[4][8][4];
    #pragma unroll
    for (int i = 0; i < 4; i++)
        #pragma unroll
        for (int j = 0; j < 8; j++)
            #pragma unroll
            for (int k = 0; k < 4; k++) acc[i][j][k] = 0.f;

    // cp.async chunk mapping (16B chunks from contiguous panels)
    const int aM   = tid >> 2;           // A rows 0..63 (+64)
    const int aPrt = tid & 3;
    const int bN   = tid >> 2;           // B rows 0..63 (+64,128,192)
    const int bPrt = tid & 3;

    const __half* Apan = g_Wh + ((size_t)m0) * 32;  // + t*SS*32 per tile
    const __half* Bpan = g_Hp + ((size_t)n0) * 32;  // + t*NN*32 per tile

    #define ISSUE(t, st)                                                          \
        do {                                                                      \
            const __half* asrc = Apan + (size_t)(t) * SS * 32;                    \
            const __half* bsrc = Bpan + (size_t)(t) * NN * 32;                    \
            _Pragma("unroll")                                                     \
            for (int j = 0; j < 2; j++) {                                         \
                int m = aM + j * 64;                                              \
                cp16(sb + (st) * AST + m * 80 + aPrt * 16,                        \
                     asrc + (size_t)m * 32 + aPrt * 8);                           \
            }                                                                     \
            _Pragma("unroll")                                                     \
            for (int j = 0; j < 4; j++) {                                         \
                int n = bN + j * 64;                                              \
                cp16(sb + OFF_BS + (st) * BST + n * 80 + bPrt * 16,               \
                     bsrc + (size_t)n * 32 + bPrt * 8);                           \
            }                                                                     \
        } while (0)

    // ldmatrix base addresses
    const int l15 = lane & 15;
    const int lhi = lane >> 4;
    const uint32_t aLd = sb + (wm + l15) * 80 + lhi * 16;
    const uint32_t bLd = sb + OFF_BS + (wn + l15) * 80 + lhi * 16;

    // prologue: stages 0,1
    ISSUE(0, 0); CP_COMMIT();
    ISSUE(1, 1); CP_COMMIT();

    for (int t = 0; t < NT; t++) {
        const int st = t % 3;
        CP_WAIT1();
        __syncthreads();
        if (t + 2 < NT) ISSUE(t + 2, (t + 2) % 3);
        CP_COMMIT();

        #pragma unroll
        for (int ks = 0; ks < 2; ks++) {
            uint32_t a[4][4], bm_[4][4];
            #pragma unroll
            for (int i = 0; i < 4; i++)
                ldmatrix_x4(a[i][0], a[i][1], a[i][2], a[i][3],
                            aLd + st * AST + i * 16 * 80 + ks * 32);
            #pragma unroll
            for (int j = 0; j < 4; j++)
                ldmatrix_x4(bm_[j][0], bm_[j][1], bm_[j][2], bm_[j][3],
                            bLd + st * BST + j * 16 * 80 + ks * 32);
            #pragma unroll
            for (int i = 0; i < 4; i++)
                #pragma unroll
                for (int j = 0; j < 4; j++) {
                    mma_f16(acc[i][2*j    ], a[i], bm_[j][0], bm_[j][2]);
                    mma_f16(acc[i][2*j + 1], a[i], bm_[j][1], bm_[j][3]);
                }
        }
    }

    // Epilogue: n -> (batch, channel); whole CTA sits in one batch.
    const int bidx = n0 >> 9;
    const int c0   = n0 & 511;
    const float* xb = x   + (size_t)bidx * SC;
    float*       ob = out + (size_t)bidx * SC;

    #pragma unroll
    for (int i = 0; i < 4; i++) {
        const int t0 = m0 + wm + i * 16 + (lane >> 2);
        const float bias0 = __ldg(linb + t0);
        const float bias1 = __ldg(linb + t0 + 8);
        #pragma unroll
        for (int j = 0; j < 8; j++) {
            const int c = c0 + wn + j * 8 + (lane & 3) * 2;
            float2 xv0 = *reinterpret_cast<const float2*>(xb + (size_t)t0 * CC + c);
            float2 o0;
            o0.x = xv0.x + fmaxf(acc[i][j][0] + bias0, 0.f);
            o0.y = xv0.y + fmaxf(acc[i][j][1] + bias0, 0.f);
            *reinterpret_cast<float2*>(ob + (size_t)t0 * CC + c) = o0;

            float2 xv1 = *reinterpret_cast<const float2*>(xb + (size_t)(t0 + 8) * CC + c);
            float2 o1;
            o1.x = xv1.x + fmaxf(acc[i][j][2] + bias1, 0.f);
            o1.y = xv1.y + fmaxf(acc[i][j][3] + bias1, 0.f);
            *reinterpret_cast<float2*>(ob + (size_t)(t0 + 8) * CC + c) = o1;
        }
    }
}

// ---------------------------------------------------------------------------
// Launch
// ---------------------------------------------------------------------------
extern "C" void kernel_launch(void* const* d_in, const int* in_sizes, int n_in,
                              void* d_out, int out_size) {
    const float* x     = (const float*)d_in[0];
    const float* ln_w  = (const float*)d_in[1];
    const float* ln_b  = (const float*)d_in[2];
    const float* lin_w = (const float*)d_in[3];
    const float* lin_b = (const float*)d_in[4];
    float* out = (float*)d_out;

    cudaFuncSetAttribute(gemm_f16, cudaFuncAttributeMaxDynamicSharedMemorySize, GSMEM);

    reduce_kernel<<<BB * RED_CHUNKS, 256>>>(x);
    stats_kernel<<<1, 64>>>();
    convert_w_kernel<<<dim3(32, 32), dim3(32, 8)>>>(lin_w);
    normalize_t_kernel<<<dim3(SS / 32, CC / 32, BB), dim3(32, 8)>>>(x, ln_w, ln_b);

    // M=1024 (8 x 128), N=32768 (128 x 256)
    gemm_f16<<<dim3(8, 128), 256, GSMEM>>>(lin_b, x, out);
}

// round 7
// speedup vs baseline: 1.7184x; 1.0012x over previous
#include <cuda_runtime.h>
#include <cuda_fp16.h>
#include <cstdint>

// Problem constants
#define BB 64
#define SS 1024
#define CC 512
#define SC (SS*CC)
#define NN (BB*CC)          // 32768 = total N of the big GEMM
#define EPS 1e-5f
#define RED_CHUNKS 64
#define BK 32               // k-tile (halves)
#define NT (SS / BK)        // 32 k-tiles

// Scratch (device globals; 16B-aligned for cp.async / uint4)
__device__ float2 g_partials[BB * RED_CHUNKS];
__device__ float2 g_stats[BB];
// K-panel layouts: [(kt*ROWS + row)*32 + ks], fp16
__device__ __align__(16) __half g_Hp[(size_t)NN * SS];     // B panels (64MB)
__device__ __align__(16) __half g_Wh[(size_t)SS * SS];     // A panels (2MB)

// ---------------------------------------------------------------------------
// helpers
// ---------------------------------------------------------------------------
__device__ __forceinline__ uint32_t smem_to_u32(const void* p) {
    uint32_t a;
    asm("{ .reg .u64 t; cvta.to.shared.u64 t, %1; cvt.u32.u64 %0, t; }" : "=r"(a) : "l"(p));
    return a;
}
__device__ __forceinline__ void ldmatrix_x4(uint32_t& r0, uint32_t& r1,
                                            uint32_t& r2, uint32_t& r3, uint32_t addr) {
    asm volatile("ldmatrix.sync.aligned.m8n8.x4.shared.b16 {%0,%1,%2,%3}, [%4];"
                 : "=r"(r0), "=r"(r1), "=r"(r2), "=r"(r3) : "r"(addr));
}
__device__ __forceinline__ void mma_f16(float* d, const uint32_t* a,
                                        uint32_t b0, uint32_t b1) {
    asm volatile(
        "mma.sync.aligned.m16n8k16.row.col.f32.f16.f16.f32 "
        "{%0,%1,%2,%3}, {%4,%5,%6,%7}, {%8,%9}, {%0,%1,%2,%3};"
        : "+f"(d[0]), "+f"(d[1]), "+f"(d[2]), "+f"(d[3])
        : "r"(a[0]), "r"(a[1]), "r"(a[2]), "r"(a[3]), "r"(b0), "r"(b1));
}
__device__ __forceinline__ void cp16(uint32_t dst, const void* src) {
    asm volatile("cp.async.cg.shared.global [%0], [%1], 16;" :: "r"(dst), "l"(src));
}
#define CP_COMMIT() asm volatile("cp.async.commit_group;" ::: "memory")
#define CP_WAIT1()  asm volatile("cp.async.wait_group 1;" ::: "memory")

__device__ __forceinline__ uint32_t pack2(float a, float b) {
    __half2 h = __floats2half2_rn(a, b);
    return *reinterpret_cast<uint32_t*>(&h);
}

// ---------------------------------------------------------------------------
// Kernel 1: per-batch partial sums (sum, sumsq). Deterministic fixed tree.
// ---------------------------------------------------------------------------
__global__ void reduce_kernel(const float* __restrict__ x) {
    const int b     = blockIdx.x / RED_CHUNKS;
    const int chunk = blockIdx.x % RED_CHUNKS;
    const int n4    = SC / RED_CHUNKS / 4;
    const float4* px = reinterpret_cast<const float4*>(x + (size_t)b * SC) + (size_t)chunk * n4;

    float s = 0.f, sq = 0.f;
    for (int i = threadIdx.x; i < n4; i += blockDim.x) {
        float4 v = px[i];
        s  += v.x + v.y + v.z + v.w;
        sq += v.x*v.x + v.y*v.y + v.z*v.z + v.w*v.w;
    }
    __shared__ float ss[8], ssq[8];
    #pragma unroll
    for (int o = 16; o > 0; o >>= 1) {
        s  += __shfl_down_sync(0xffffffff, s,  o);
        sq += __shfl_down_sync(0xffffffff, sq, o);
    }
    if ((threadIdx.x & 31) == 0) { ss[threadIdx.x >> 5] = s; ssq[threadIdx.x >> 5] = sq; }
    __syncthreads();
    if (threadIdx.x == 0) {
        float ts = 0.f, tsq = 0.f;
        #pragma unroll
        for (int w = 0; w < 8; w++) { ts += ss[w]; tsq += ssq[w]; }
        g_partials[blockIdx.x] = make_float2(ts, tsq);
    }
}

__global__ void stats_kernel() {
    int b = threadIdx.x;
    if (b < BB) {
        float s = 0.f, sq = 0.f;
        #pragma unroll 8
        for (int i = 0; i < RED_CHUNKS; i++) {
            float2 p = g_partials[b * RED_CHUNKS + i];
            s += p.x; sq += p.y;
        }
        float mu  = s / (float)SC;
        float var = fmaxf(sq / (float)SC - mu * mu, 0.f);
        g_stats[b] = make_float2(mu, rsqrtf(var + EPS));
    }
}

// ---------------------------------------------------------------------------
// Kernel 2b: convert W (fp32 [m][s]) -> g_Wh fp16 K-panels [(kt*1024+m)*32+ks].
// 32x32 tiles. 128 uint4 write tasks (idx < 128 guard). grid (32,32), block (32,8).
// ---------------------------------------------------------------------------
__global__ void convert_w_kernel(const float* __restrict__ W) {
    __shared__ float tile[32][33];
    const int m0 = blockIdx.x * 32;
    const int s0 = blockIdx.y * 32;
    #pragma unroll
    for (int i = 0; i < 4; i++)
        tile[threadIdx.y + i * 8][threadIdx.x] =
            W[(size_t)(m0 + threadIdx.y + i * 8) * SS + s0 + threadIdx.x];
    __syncthreads();
    const int idx = threadIdx.y * 32 + threadIdx.x;
    if (idx < 128) {
        const int m     = idx >> 2;
        const int chunk = idx & 3;
        const int kt    = s0 >> 5;
        uint4 pk;
        pk.x = pack2(tile[m][chunk*8+0], tile[m][chunk*8+1]);
        pk.y = pack2(tile[m][chunk*8+2], tile[m][chunk*8+3]);
        pk.z = pack2(tile[m][chunk*8+4], tile[m][chunk*8+5]);
        pk.w = pack2(tile[m][chunk*8+6], tile[m][chunk*8+7]);
        *reinterpret_cast<uint4*>(g_Wh + ((size_t)kt * SS + m0 + m) * 32 + chunk * 8) = pk;
    }
}

// ---------------------------------------------------------------------------
// Kernel 3: fused LayerNorm + transpose -> g_Hp K-panels [(kt*NN + n)*32 + ks].
// block (32,8), grid (S/32, C/32, B). 128 uint4 write tasks (idx < 128 guard).
// ---------------------------------------------------------------------------
__global__ void normalize_t_kernel(const float* __restrict__ x,
                                   const float* __restrict__ lnw,
                                   const float* __restrict__ lnb) {
    __shared__ float tile[32][33];     // [s_local][c_local]
    const int b  = blockIdx.z;
    const int s0 = blockIdx.x * 32;
    const int c0 = blockIdx.y * 32;
    const float2 st = g_stats[b];

    #pragma unroll
    for (int i = 0; i < 4; i++) {
        int s = s0 + threadIdx.y + i * 8;
        int c = c0 + threadIdx.x;
        float v  = x  [(size_t)b * SC + (size_t)s * CC + c];
        float w  = lnw[(size_t)s * CC + c];
        float bb = lnb[(size_t)s * CC + c];
        tile[threadIdx.y + i * 8][threadIdx.x] = (v - st.x) * st.y * w + bb;
    }
    __syncthreads();
    const int idx = threadIdx.y * 32 + threadIdx.x;
    if (idx < 128) {
        const int c     = idx >> 2;
        const int chunk = idx & 3;
        const int kt    = s0 >> 5;
        const int n     = b * CC + c0 + c;
        uint4 pk;
        pk.x = pack2(tile[chunk*8+0][c], tile[chunk*8+1][c]);
        pk.y = pack2(tile[chunk*8+2][c], tile[chunk*8+3][c]);
        pk.z = pack2(tile[chunk*8+4][c], tile[chunk*8+5][c]);
        pk.w = pack2(tile[chunk*8+6][c], tile[chunk*8+7][c]);
        *reinterpret_cast<uint4*>(g_Hp + ((size_t)kt * NN + n) * 32 + chunk * 8) = pk;
    }
}

// ---------------------------------------------------------------------------
// Kernel 4: fp16 GEMM, fp32 acc. D[1024, 32768] = Wh x Hp^T, K=1024.
// CTA 128(M) x 256(N) x 32(K). 512 threads, 16 warps (2M x 8N), warp 64x32.
// 3-stage cp.async pipeline from contiguous K-panels.
// smem rows 80B (conflict-free ldmatrix). Epilogue: out = x + relu(D + bias).
// ---------------------------------------------------------------------------
#define BM 128
#define BN 256
#define AST (BM * 80)              // 10240 B per A stage
#define BST (BN * 80)              // 20480 B per B stage
#define OFF_BS (3 * AST)           // B stages base
#define GSMEM (3 * (AST + BST))    // 92160 B

__global__ __launch_bounds__(512, 1)
void gemm_f16(const float* __restrict__ linb,
              const float* __restrict__ x, float* __restrict__ out)
{
    extern __shared__ char smem[];
    const uint32_t sb = smem_to_u32(smem);

    const int tid  = threadIdx.x;
    const int lane = tid & 31;
    const int wid  = tid >> 5;
    const int wm   = (wid >> 3) * 64;       // 0 / 64
    const int wn   = (wid & 7) * 32;        // 0..224
    const int m0   = blockIdx.x * BM;
    const int n0   = blockIdx.y * BN;

    float acc[4][4][4];
    #pragma unroll
    for (int i = 0; i < 4; i++)
        #pragma unroll
        for (int j = 0; j < 4; j++)
            #pragma unroll
            for (int k = 0; k < 4; k++) acc[i][j][k] = 0.f;

    // cp.async chunk mapping (16B chunks from contiguous panels, 512 threads)
    const int aRow = tid >> 2;           // A: 128 rows x 4 chunks = 512 = 1/thread
    const int aPrt = tid & 3;
    const int bRow = tid >> 2;           // B: 256 rows x 4 chunks = 1024 = 2/thread
    const int bPrt = tid & 3;

    const __half* Apan = g_Wh + ((size_t)m0) * 32;  // + t*SS*32 per tile
    const __half* Bpan = g_Hp + ((size_t)n0) * 32;  // + t*NN*32 per tile

    #define ISSUE(t, st)                                                          \
        do {                                                                      \
            const __half* asrc = Apan + (size_t)(t) * SS * 32;                    \
            const __half* bsrc = Bpan + (size_t)(t) * NN * 32;                    \
            cp16(sb + (st) * AST + aRow * 80 + aPrt * 16,                         \
                 asrc + (size_t)aRow * 32 + aPrt * 8);                            \
            _Pragma("unroll")                                                     \
            for (int j = 0; j < 2; j++) {                                         \
                int n = bRow + j * 128;                                           \
                cp16(sb + OFF_BS + (st) * BST + n * 80 + bPrt * 16,               \
                     bsrc + (size_t)n * 32 + bPrt * 8);                           \
            }                                                                     \
        } while (0)

    // ldmatrix base addresses
    const int l15 = lane & 15;
    const int lhi = lane >> 4;
    const uint32_t aLd = sb + (wm + l15) * 80 + lhi * 16;
    const uint32_t bLd = sb + OFF_BS + (wn + l15) * 80 + lhi * 16;

    // prologue: stages 0,1
    ISSUE(0, 0); CP_COMMIT();
    ISSUE(1, 1); CP_COMMIT();

    for (int t = 0; t < NT; t++) {
        const int st = t % 3;
        CP_WAIT1();
        __syncthreads();
        if (t + 2 < NT) ISSUE(t + 2, (t + 2) % 3);
        CP_COMMIT();

        #pragma unroll
        for (int ks = 0; ks < 2; ks++) {
            uint32_t a[4][4], bm_[2][4];
            #pragma unroll
            for (int i = 0; i < 4; i++)
                ldmatrix_x4(a[i][0], a[i][1], a[i][2], a[i][3],
                            aLd + st * AST + i * 16 * 80 + ks * 32);
            #pragma unroll
            for (int j = 0; j < 2; j++)
                ldmatrix_x4(bm_[j][0], bm_[j][1], bm_[j][2], bm_[j][3],
                            bLd + st * BST + j * 16 * 80 + ks * 32);
            #pragma unroll
            for (int i = 0; i < 4; i++)
                #pragma unroll
                for (int j = 0; j < 2; j++) {
                    mma_f16(acc[i][2*j    ], a[i], bm_[j][0], bm_[j][2]);
                    mma_f16(acc[i][2*j + 1], a[i], bm_[j][1], bm_[j][3]);
                }
        }
    }

    // Epilogue: n -> (batch, channel); whole CTA sits in one batch.
    const int bidx = n0 >> 9;
    const int c0   = n0 & 511;
    const float* xb = x   + (size_t)bidx * SC;
    float*       ob = out + (size_t)bidx * SC;

    #pragma unroll
    for (int i = 0; i < 4; i++) {
        const int t0 = m0 + wm + i * 16 + (lane >> 2);
        const float bias0 = __ldg(linb + t0);
        const float bias1 = __ldg(linb + t0 + 8);
        #pragma unroll
        for (int j = 0; j < 4; j++) {
            const int c = c0 + wn + j * 8 + (lane & 3) * 2;
            float2 xv0 = *reinterpret_cast<const float2*>(xb + (size_t)t0 * CC + c);
            float2 o0;
            o0.x = xv0.x + fmaxf(acc[i][j][0] + bias0, 0.f);
            o0.y = xv0.y + fmaxf(acc[i][j][1] + bias0, 0.f);
            *reinterpret_cast<float2*>(ob + (size_t)t0 * CC + c) = o0;

            float2 xv1 = *reinterpret_cast<const float2*>(xb + (size_t)(t0 + 8) * CC + c);
            float2 o1;
            o1.x = xv1.x + fmaxf(acc[i][j][2] + bias1, 0.f);
            o1.y = xv1.y + fmaxf(acc[i][j][3] + bias1, 0.f);
            *reinterpret_cast<float2*>(ob + (size_t)(t0 + 8) * CC + c) = o1;
        }
    }
}

// ---------------------------------------------------------------------------
// Launch
// ---------------------------------------------------------------------------
extern "C" void kernel_launch(void* const* d_in, const int* in_sizes, int n_in,
                              void* d_out, int out_size) {
    const float* x     = (const float*)d_in[0];
    const float* ln_w  = (const float*)d_in[1];
    const float* ln_b  = (const float*)d_in[2];
    const float* lin_w = (const float*)d_in[3];
    const float* lin_b = (const float*)d_in[4];
    float* out = (float*)d_out;

    cudaFuncSetAttribute(gemm_f16, cudaFuncAttributeMaxDynamicSharedMemorySize, GSMEM);

    reduce_kernel<<<BB * RED_CHUNKS, 256>>>(x);
    stats_kernel<<<1, 64>>>();
    convert_w_kernel<<<dim3(32, 32), dim3(32, 8)>>>(lin_w);
    normalize_t_kernel<<<dim3(SS / 32, CC / 32, BB), dim3(32, 8)>>>(x, ln_w, ln_b);

    // M=1024 (8 x 128), N=32768 (128 x 256)
    gemm_f16<<<dim3(8, 128), 512, GSMEM>>>(lin_b, x, out);
}